// round 2
// baseline (speedup 1.0000x reference)
#include <cuda_runtime.h>
#include <cstdint>

// ============================================================================
// FourierKARTLayer: V[b,s,d] = sum_{q,k} A[d,q,k] * sin(k*(C_q + w_q*t) + Bp[d,q,k])
//   C = X0 @ Wc_w^T + Wc_b
// Decomposition:
//   W2[(kk*128+q), d] = A[d,q,k]*cos(Bp) (kk=k-1, sin part) / A[d,q,k]*sin(Bp) (kk=k+5, cos part)
//   F[token, f] = sin(k*angle) / cos(k*angle)  via one sincos + harmonic recurrence
//   V = F @ W2
// ============================================================================

#define D_INF   256
#define D_OUTF  64
#define NQ      128
#define NK      6
#define NTOK    2048
#define SEQ     1024
#define TPB     256
#define TOKB    4
#define NFEAT   1536       // 12 * 128

__device__ float  g_WcTd[D_INF * NQ * 2];   // [i][q] duplicated pairs (w,w)
__device__ float  g_W2[NFEAT * D_OUTF];     // [f][d]  (d contiguous)

using u64 = unsigned long long;

__device__ __forceinline__ u64 pack2(float x, float y) {
    u64 r; asm("mov.b64 %0, {%1, %2};" : "=l"(r) : "f"(x), "f"(y)); return r;
}
__device__ __forceinline__ u64 fma2(u64 a, u64 b, u64 c) {
    u64 d; asm("fma.rn.f32x2 %0, %1, %2, %3;" : "=l"(d) : "l"(a), "l"(b), "l"(c)); return d;
}
__device__ __forceinline__ float2 unpack2(u64 a) {
    float2 f; asm("mov.b64 {%0, %1}, %2;" : "=f"(f.x), "=f"(f.y) : "l"(a)); return f;
}
__device__ __forceinline__ u64 add2(u64 a, u64 b) {
    u64 d; asm("add.rn.f32x2 %0, %1, %2;" : "=l"(d) : "l"(a), "l"(b)); return d;
}

// ----------------------------------------------------------------------------
// Prep: fold Bp into W2; duplicate-transpose Wc.
// ----------------------------------------------------------------------------
__global__ void prep_kernel(const float* __restrict__ Wc_w,
                            const float* __restrict__ A,
                            const float* __restrict__ Bp) {
    int n = blockIdx.x * blockDim.x + threadIdx.x;
    if (n < NFEAT * D_OUTF) {
        int d  = n & (D_OUTF - 1);
        int f  = n >> 6;
        int q  = f & (NQ - 1);
        int kk = f >> 7;                       // 0..11
        int k  = (kk >= NK) ? (kk - NK) : kk;  // 0..5
        int src = (d * NQ + q) * NK + k;
        float a  = A[src];
        float bp = Bp[src];
        float nr = rintf(bp * 0.15915494309189535f);
        float br = fmaf(nr, -6.283185307179586f, bp);
        float sb, cb;
        __sincosf(br, &sb, &cb);
        g_W2[n] = (kk < NK) ? (a * cb) : (a * sb);
    }
    if (n < D_INF * NQ) {
        int q = n & (NQ - 1);
        int i = n >> 7;
        float v = Wc_w[q * D_INF + i];
        ((float2*)g_WcTd)[n] = make_float2(v, v);   // [i][q] dup pair
    }
}

// ----------------------------------------------------------------------------
// Main fused kernel: 512 blocks x 4 tokens, 256 threads, 4 blocks/SM.
// smem (floats): XT [0,1024) | Fdup [1024,13312) | E [13312,13824)
// ----------------------------------------------------------------------------
__global__ void __launch_bounds__(TPB, 4) main_kernel(
    const float* __restrict__ X0,
    const float* __restrict__ t,
    const float* __restrict__ Wc_b,
    const float* __restrict__ w,
    float* __restrict__ V) {

    extern __shared__ float smem[];
    float* XT = smem;                 // [256 i][4 tok]
    float* Fd = smem + 1024;          // [1536 f][8]: t0 t0 t1 t1 t2 t2 t3 t3
    u64*   E  = (u64*)(smem + 13312); // [256] exchange

    const int tid = threadIdx.x;
    const int g0  = blockIdx.x * TOKB;
    const float tb = t[g0 / SEQ];

    // ---- Phase A: load + transpose X tile (4 tokens x 256 feats) --------
    {
        int tk  = tid >> 6;           // token 0..3
        int seg = tid & 63;           // 64 segs x 4 feats
        float4 v = *(const float4*)(X0 + (size_t)(g0 + tk) * D_INF + seg * 4);
        int i0 = seg * 4;
        XT[(i0 + 0) * TOKB + tk] = v.x;
        XT[(i0 + 1) * TOKB + tk] = v.y;
        XT[(i0 + 2) * TOKB + tk] = v.z;
        XT[(i0 + 3) * TOKB + tk] = v.w;
    }
    __syncthreads();

    // ---- Phase B: GEMM1 (angles, i-split) + sincos + harmonics ----------
    {
        const int q  = tid & (NQ - 1);
        const int ih = tid >> 7;                // i-half 0/1
        float init = (ih == 0) ? fmaf(w[q], tb, Wc_b[q]) : 0.f;
        u64 a01 = pack2(init, init);            // tokens 0,1
        u64 a23 = pack2(init, init);            // tokens 2,3
        const u64* wdp = (const u64*)g_WcTd + q;
        const int ibase = ih * (D_INF / 2);

        #pragma unroll 8
        for (int i = 0; i < D_INF / 2; i++) {
            u64 wd = __ldg(wdp + (ibase + i) * NQ);
            ulonglong2 xv = *(const ulonglong2*)(XT + (ibase + i) * TOKB);
            a01 = fma2(xv.x, wd, a01);
            a23 = fma2(xv.y, wd, a23);
        }

        // cross-half exchange: (q,0) keeps t0/t1, (q,1) keeps t2/t3
        E[ih ? (NQ + q) : q] = ih ? a01 : a23;
        __syncthreads();
        u64 tot = ih ? add2(a23, E[q]) : add2(a01, E[NQ + q]);

        float2 ang = unpack2(tot);
        // range reduce + sincos for the two tokens this thread owns
        float n0 = rintf(ang.x * 0.15915494309189535f);
        float n1 = rintf(ang.y * 0.15915494309189535f);
        float r0 = fmaf(n0, -6.283185307179586f, ang.x);
        float r1 = fmaf(n1, -6.283185307179586f, ang.y);
        float s1a, c1a, s1b, c1b;
        __sincosf(r0, &s1a, &c1a);
        __sincosf(r1, &s1b, &c1b);
        float ska = s1a, cka = c1a, skb = s1b, ckb = c1b;
        float* base = Fd + q * 8 + ih * 4;      // our 4-float quadrant of each row
        #pragma unroll
        for (int k = 0; k < NK; k++) {
            *(float4*)(base + (k * NQ) * 8)        = make_float4(ska, ska, skb, skb);
            *(float4*)(base + ((k + NK) * NQ) * 8) = make_float4(cka, cka, ckb, ckb);
            float nsa = fmaf(ska, c1a, cka * s1a);
            float nca = fmaf(cka, c1a, -ska * s1a);
            float nsb = fmaf(skb, c1b, ckb * s1b);
            float ncb = fmaf(ckb, c1b, -skb * s1b);
            ska = nsa; cka = nca; skb = nsb; ckb = ncb;
        }
    }
    __syncthreads();

    // ---- Phase C: GEMM2, d-packed accumulators, no dup MOVs -------------
    // thread = (fs 0..15, dg 0..15); f = ff*16 + fs (interleaved slices)
    const int fs = tid >> 4;
    const int dg = tid & 15;
    u64 acc[2][4];                    // [d-pair][token]
    #pragma unroll
    for (int a = 0; a < 2; a++)
        #pragma unroll
        for (int b = 0; b < 4; b++) acc[a][b] = 0ULL;

    const float* w2base = g_W2 + fs * D_OUTF + dg * 4;   // + ff*16*64
    const float* fbase  = Fd + fs * 8;                   // + ff*16*8

    #pragma unroll 4
    for (int ff = 0; ff < NFEAT / 16; ff++) {
        ulonglong2 wp = __ldg((const ulonglong2*)(w2base + ff * 1024)); // (d0,d1),(d2,d3)
        const u64* fp = (const u64*)(fbase + ff * 128);
        u64 f0 = fp[0], f1 = fp[1], f2 = fp[2], f3 = fp[3];  // (tj,tj) dup pairs
        acc[0][0] = fma2(f0, wp.x, acc[0][0]);
        acc[0][1] = fma2(f1, wp.x, acc[0][1]);
        acc[0][2] = fma2(f2, wp.x, acc[0][2]);
        acc[0][3] = fma2(f3, wp.x, acc[0][3]);
        acc[1][0] = fma2(f0, wp.y, acc[1][0]);
        acc[1][1] = fma2(f1, wp.y, acc[1][1]);
        acc[1][2] = fma2(f2, wp.y, acc[1][2]);
        acc[1][3] = fma2(f3, wp.y, acc[1][3]);
    }

    // ---- Reduce over 16 f-slices ----------------------------------------
    __syncthreads();                  // Fd reads done; reuse smem
    float* R = smem;                  // [16][4 tok][64 d]
    #pragma unroll
    for (int dp = 0; dp < 2; dp++)
        #pragma unroll
        for (int tk = 0; tk < 4; tk++)
            *(u64*)(R + fs * 256 + tk * 64 + dg * 4 + dp * 2) = acc[dp][tk];
    __syncthreads();

    {
        int tk = tid >> 6;
        int d  = tid & 63;
        float s = 0.f;
        #pragma unroll
        for (int j = 0; j < 16; j++)
            s += R[j * 256 + tk * 64 + d];
        V[(size_t)(g0 + tk) * D_OUTF + d] = s;
    }
}

// ----------------------------------------------------------------------------
extern "C" void kernel_launch(void* const* d_in, const int* in_sizes, int n_in,
                              void* d_out, int out_size) {
    const float* X0   = (const float*)d_in[0];
    const float* t    = (const float*)d_in[1];
    const float* Wc_w = (const float*)d_in[2];
    const float* Wc_b = (const float*)d_in[3];
    const float* w    = (const float*)d_in[4];
    const float* A    = (const float*)d_in[5];
    const float* Bp   = (const float*)d_in[6];
    float* V = (float*)d_out;

    const int smem_bytes = 13824 * (int)sizeof(float);   // 55296 B
    static int configured = 0;
    cudaFuncSetAttribute(main_kernel, cudaFuncAttributeMaxDynamicSharedMemorySize, smem_bytes);
    (void)configured;

    prep_kernel<<<(NFEAT * D_OUTF + 255) / 256, 256>>>(Wc_w, A, Bp);
    main_kernel<<<NTOK / TOKB, TPB, smem_bytes>>>(X0, t, Wc_b, w, V);
}

// round 3
// speedup vs baseline: 1.1209x; 1.1209x over previous
#include <cuda_runtime.h>
#include <cstdint>

// ============================================================================
// FourierKARTLayer: V = F @ W2, F from sincos(harmonics of X0@WcT + bias + w*t)
// ============================================================================

#define D_INF   256
#define D_OUTF  64
#define NQ      128
#define NK      6
#define NTOK    2048
#define SEQ     1024
#define TPB     256
#define TOKB    8
#define NFEAT   1536       // 12 * 128

__device__ float g_WcT[D_INF * NQ];     // [i][q]  (q contiguous, non-dup)
__device__ float g_W2[NFEAT * D_OUTF];  // [f][d]  (d contiguous)

using u64 = unsigned long long;

__device__ __forceinline__ u64 pack2(float x, float y) {
    u64 r; asm("mov.b64 %0, {%1, %2};" : "=l"(r) : "f"(x), "f"(y)); return r;
}
__device__ __forceinline__ u64 fma2(u64 a, u64 b, u64 c) {
    u64 d; asm("fma.rn.f32x2 %0, %1, %2, %3;" : "=l"(d) : "l"(a), "l"(b), "l"(c)); return d;
}
__device__ __forceinline__ float2 unpack2(u64 a) {
    float2 f; asm("mov.b64 {%0, %1}, %2;" : "=f"(f.x), "=f"(f.y) : "l"(a)); return f;
}
__device__ __forceinline__ u64 add2(u64 a, u64 b) {
    u64 d; asm("add.rn.f32x2 %0, %1, %2;" : "=l"(d) : "l"(a), "l"(b)); return d;
}

// ----------------------------------------------------------------------------
__global__ void prep_kernel(const float* __restrict__ Wc_w,
                            const float* __restrict__ A,
                            const float* __restrict__ Bp) {
    int n = blockIdx.x * blockDim.x + threadIdx.x;
    if (n < NFEAT * D_OUTF) {
        int d  = n & (D_OUTF - 1);
        int f  = n >> 6;
        int q  = f & (NQ - 1);
        int kk = f >> 7;                       // 0..11
        int k  = (kk >= NK) ? (kk - NK) : kk;  // 0..5
        int src = (d * NQ + q) * NK + k;
        float a  = A[src];
        float bp = Bp[src];
        float nr = rintf(bp * 0.15915494309189535f);
        float br = fmaf(nr, -6.283185307179586f, bp);
        float sb, cb;
        __sincosf(br, &sb, &cb);
        g_W2[n] = (kk < NK) ? (a * cb) : (a * sb);
    }
    if (n < D_INF * NQ) {
        int q = n & (NQ - 1);
        int i = n >> 7;
        g_WcT[n] = Wc_w[q * D_INF + i];
    }
}

// ----------------------------------------------------------------------------
// Main kernel: 256 blocks x 8 tokens, 256 threads.
// smem = 48KB, aliased: Xs [0,8K) -> E [0,32K) -> Fs [0,48K) -> R [0,32K)
// ----------------------------------------------------------------------------
__global__ void __launch_bounds__(TPB) main_kernel(
    const float* __restrict__ X0,
    const float* __restrict__ t,
    const float* __restrict__ Wc_b,
    const float* __restrict__ w,
    float* __restrict__ V) {

    extern __shared__ float smem[];
    float* Xs = smem;            // [256 i][8 tok]
    u64*   E  = (u64*)smem;      // [16 slot][8 ih][32 qg]
    float* Fs = smem;            // [1536 f][8 tok]

    const int tid = threadIdx.x;
    const int g0  = blockIdx.x * TOKB;
    const float tb = t[g0 >> 10];

    // ---- Phase A: load + transpose X (8 tok x 256 i) --------------------
    {
        int tok = tid >> 5;
        int seg = tid & 31;
        const float4* src = (const float4*)(X0 + (size_t)(g0 + tok) * D_INF + seg * 8);
        float4 v0 = src[0];
        float4 v1 = src[1];
        int i0 = seg * 8;
        Xs[(i0 + 0) * TOKB + tok] = v0.x;
        Xs[(i0 + 1) * TOKB + tok] = v0.y;
        Xs[(i0 + 2) * TOKB + tok] = v0.z;
        Xs[(i0 + 3) * TOKB + tok] = v0.w;
        Xs[(i0 + 4) * TOKB + tok] = v1.x;
        Xs[(i0 + 5) * TOKB + tok] = v1.y;
        Xs[(i0 + 6) * TOKB + tok] = v1.z;
        Xs[(i0 + 7) * TOKB + tok] = v1.w;
    }
    __syncthreads();

    // ---- Phase B1: GEMM1 accumulate (thread = ih x qg, 4q x 8tok) -------
    // Warp shares one X row (full broadcast, 2 distinct LDS addrs).
    {
        const int ih = tid >> 5;       // i chunk: 32 i's
        const int qg = tid & 31;       // 4 q's
        u64 acc[4][4];                 // [qi][token-pair]
        #pragma unroll
        for (int a = 0; a < 4; a++)
            #pragma unroll
            for (int b = 0; b < 4; b++) acc[a][b] = 0ULL;

        #pragma unroll 4
        for (int s = 0; s < 32; s++) {
            int i = ih * 32 + s;
            ulonglong2 x01 = *(const ulonglong2*)(Xs + i * TOKB);       // pairs t01,t23
            ulonglong2 x23 = *(const ulonglong2*)(Xs + i * TOKB + 4);   // pairs t45,t67
            float4 wv = __ldg((const float4*)(g_WcT + i * NQ + qg * 4));
            u64 w0 = pack2(wv.x, wv.x);
            u64 w1 = pack2(wv.y, wv.y);
            u64 w2 = pack2(wv.z, wv.z);
            u64 w3 = pack2(wv.w, wv.w);
            acc[0][0] = fma2(x01.x, w0, acc[0][0]);
            acc[0][1] = fma2(x01.y, w0, acc[0][1]);
            acc[0][2] = fma2(x23.x, w0, acc[0][2]);
            acc[0][3] = fma2(x23.y, w0, acc[0][3]);
            acc[1][0] = fma2(x01.x, w1, acc[1][0]);
            acc[1][1] = fma2(x01.y, w1, acc[1][1]);
            acc[1][2] = fma2(x23.x, w1, acc[1][2]);
            acc[1][3] = fma2(x23.y, w1, acc[1][3]);
            acc[2][0] = fma2(x01.x, w2, acc[2][0]);
            acc[2][1] = fma2(x01.y, w2, acc[2][1]);
            acc[2][2] = fma2(x23.x, w2, acc[2][2]);
            acc[2][3] = fma2(x23.y, w2, acc[2][3]);
            acc[3][0] = fma2(x01.x, w3, acc[3][0]);
            acc[3][1] = fma2(x01.y, w3, acc[3][1]);
            acc[3][2] = fma2(x23.x, w3, acc[3][2]);
            acc[3][3] = fma2(x23.y, w3, acc[3][3]);
        }
        __syncthreads();               // all X reads done; E may alias X

        // E[slot = qi*4+pair][ih][qg]  (writes conflict-free: qg contiguous)
        #pragma unroll
        for (int qi = 0; qi < 4; qi++)
            #pragma unroll
            for (int p = 0; p < 4; p++)
                E[(qi * 4 + p) * 256 + ih * 32 + qg] = acc[qi][p];
    }
    __syncthreads();

    // ---- Phase B2: reduce over ih, sincos, store F ----------------------
    {
        const int q  = tid & (NQ - 1);
        const int th = tid >> 7;        // token half: tokens th*4 .. th*4+3
        const int qg = q >> 2;
        const int s0slot = (q & 3) * 4 + th * 2;
        u64 s0 = 0ULL, s1 = 0ULL;
        #pragma unroll
        for (int j = 0; j < 8; j++) {
            s0 = add2(s0, E[s0slot * 256 + j * 32 + qg]);
            s1 = add2(s1, E[(s0slot + 1) * 256 + j * 32 + qg]);
        }
        float init = fmaf(w[q], tb, Wc_b[q]);
        u64 bi = pack2(init, init);
        s0 = add2(s0, bi);
        s1 = add2(s1, bi);
        float2 a01 = unpack2(s0);
        float2 a23 = unpack2(s1);
        float ang[4] = {a01.x, a01.y, a23.x, a23.y};
        __syncthreads();                // all E reads done; F may alias E

        float sv[4], cv[4];
        #pragma unroll
        for (int j = 0; j < 4; j++) {
            float nr = rintf(ang[j] * 0.15915494309189535f);
            float ar = fmaf(nr, -6.283185307179586f, ang[j]);
            __sincosf(ar, &sv[j], &cv[j]);
        }
        float sk[4], ck[4];
        #pragma unroll
        for (int j = 0; j < 4; j++) { sk[j] = sv[j]; ck[j] = cv[j]; }
        float* base = Fs + q * TOKB + th * 4;
        #pragma unroll
        for (int k = 0; k < NK; k++) {
            *(float4*)(base + (k * NQ) * TOKB)        = make_float4(sk[0], sk[1], sk[2], sk[3]);
            *(float4*)(base + ((k + NK) * NQ) * TOKB) = make_float4(ck[0], ck[1], ck[2], ck[3]);
            #pragma unroll
            for (int j = 0; j < 4; j++) {
                float ns = fmaf(sk[j], cv[j], ck[j] * sv[j]);
                float nc = fmaf(ck[j], cv[j], -sk[j] * sv[j]);
                sk[j] = ns; ck[j] = nc;
            }
        }
    }
    __syncthreads();

    // ---- Phase C: GEMM2, thread = (fs x dg), tile 8tok x 8d -------------
    // f = j*32 + fs  -> warp's 4 fs rows consecutive: conflict-free LDS.128,
    // W2 warp LDG = 4 rows x 256B = 1KB contiguous.
    const int fs = tid >> 3;     // 0..31
    const int dg = tid & 7;      // 8 d each
    u64 acc2[32];                // [pair(4)][dd(8)]
    #pragma unroll
    for (int k = 0; k < 32; k++) acc2[k] = 0ULL;

    #pragma unroll 4
    for (int j = 0; j < NFEAT / 32; j++) {
        int f = j * 32 + fs;
        const float* frow = Fs + f * TOKB;
        ulonglong2 f01 = *(const ulonglong2*)frow;         // (t0,t1),(t2,t3)
        ulonglong2 f23 = *(const ulonglong2*)(frow + 4);   // (t4,t5),(t6,t7)
        const float* wrow = g_W2 + f * D_OUTF + dg * 8;
        float4 wa = __ldg((const float4*)wrow);
        float4 wb = __ldg((const float4*)(wrow + 4));
        float wv[8] = {wa.x, wa.y, wa.z, wa.w, wb.x, wb.y, wb.z, wb.w};
        u64 fp[4] = {f01.x, f01.y, f23.x, f23.y};
        #pragma unroll
        for (int dd = 0; dd < 8; dd++) {
            u64 wd = pack2(wv[dd], wv[dd]);
            #pragma unroll
            for (int p = 0; p < 4; p++)
                acc2[p * 8 + dd] = fma2(fp[p], wd, acc2[p * 8 + dd]);
        }
    }

    // ---- Reduction over 32 f-slices (two-step, 32KB buffer) -------------
    __syncthreads();                   // F reads done; R aliases smem
    u64* R = (u64*)smem;               // [16 combined-slot][8 dg][32 u64]
    if (fs >= 16) {
        int slot = (fs - 16) * 8 + dg;
        #pragma unroll
        for (int k = 0; k < 32; k++) R[slot * 32 + k] = acc2[k];
    }
    __syncthreads();
    if (fs < 16) {
        int slot = fs * 8 + dg;
        #pragma unroll
        for (int k = 0; k < 32; k++) acc2[k] = add2(acc2[k], R[slot * 32 + k]);
        #pragma unroll
        for (int k = 0; k < 32; k++) R[slot * 32 + k] = acc2[k];
    }
    __syncthreads();

    // ---- Final: each thread sums 16 slices for 2 outputs ----------------
    {
        const float* Rf = (const float*)R;
        int o   = 2 * tid;
        int tok = o >> 6;
        int d0  = o & 63;
        int pair = tok >> 1;
        int half = tok & 1;
        float sA = 0.f, sB = 0.f;
        #pragma unroll
        for (int sl = 0; sl < 16; sl++) {
            int ia = ((sl * 8 + (d0 >> 3)) * 32 + pair * 8 + (d0 & 7)) * 2 + half;
            int ib = ((sl * 8 + ((d0 + 1) >> 3)) * 32 + pair * 8 + ((d0 + 1) & 7)) * 2 + half;
            sA += Rf[ia];
            sB += Rf[ib];
        }
        *(float2*)(V + (size_t)(g0 + tok) * D_OUTF + d0) = make_float2(sA, sB);
    }
}

// ----------------------------------------------------------------------------
extern "C" void kernel_launch(void* const* d_in, const int* in_sizes, int n_in,
                              void* d_out, int out_size) {
    const float* X0   = (const float*)d_in[0];
    const float* t    = (const float*)d_in[1];
    const float* Wc_w = (const float*)d_in[2];
    const float* Wc_b = (const float*)d_in[3];
    const float* w    = (const float*)d_in[4];
    const float* A    = (const float*)d_in[5];
    const float* Bp   = (const float*)d_in[6];
    float* V = (float*)d_out;

    const int smem_bytes = NFEAT * TOKB * (int)sizeof(float);   // 49152 B
    cudaFuncSetAttribute(main_kernel, cudaFuncAttributeMaxDynamicSharedMemorySize, smem_bytes);

    prep_kernel<<<(NFEAT * D_OUTF + 255) / 256, 256>>>(Wc_w, A, Bp);
    main_kernel<<<NTOK / TOKB, TPB, smem_bytes>>>(X0, t, Wc_b, w, V);
}